// round 2
// baseline (speedup 1.0000x reference)
#include <cuda_runtime.h>

// L1Attn: attn[b,i,j,h] = -(1/sqrt(64)) * sum_w |q[b,j,h,w] - k[b,i,h,w]|
// q,k: [2, 512, 8, 64] fp32.  out: [2, 512(i=key), 512(j=query), 8] fp32.

#define NCTX 512
#define NH   8
#define WID  64
#define TI   16      // keys per block
#define TJ   16      // queries per block
#define WC   32      // w-chunk held in smem
#define JSTR 260     // smem row stride = NH*WC + 4 pad (bank-conflict-free, 16B aligned)
#define OSTR 132     // output staging row stride (16B aligned, <=2-way conflicts)

__device__ __forceinline__ unsigned long long addf32x2(unsigned long long a,
                                                       unsigned long long b) {
    unsigned long long r;
    asm("add.rn.f32x2 %0, %1, %2;" : "=l"(r) : "l"(a), "l"(b));
    return r;
}

__global__ void __launch_bounds__(256)
l1attn_kernel(const float* __restrict__ q, const float* __restrict__ k,
              float* __restrict__ out) {
    __shared__ float qs[TJ * JSTR];   // 4160 floats (also reused for output staging)
    __shared__ float ks[TI * JSTR];   // holds -k

    const int tid = threadIdx.x;
    const int h   = tid >> 5;    // warp id == head
    const int sub = tid & 31;
    const int ig  = sub >> 3;    // 0..3  -> i = ig + 4*r
    const int jg  = sub & 7;     // 0..7  -> j = jg + 8*jj

    const int j0 = blockIdx.x * TJ;
    const int i0 = blockIdx.y * TI;
    const int b  = blockIdx.z;

    const unsigned long long ABSM = 0x7FFFFFFF7FFFFFFFULL;

    unsigned long long acc[4][2];
#pragma unroll
    for (int r = 0; r < 4; r++) { acc[r][0] = 0ULL; acc[r][1] = 0ULL; }

    for (int wc = 0; wc < WID; wc += WC) {
        if (wc) __syncthreads();
        // Cooperative tile load: 16 rows x 8 heads x 32 w = 4096 floats per tensor.
        // 256 threads x 4 passes x float4, fully coalesced (w innermost).
#pragma unroll
        for (int pass = 0; pass < 4; pass++) {
            int idx = pass * 256 + tid;
            int w4  = idx & 7;          // float4 index within w-chunk
            int hl  = (idx >> 3) & 7;   // head
            int rl  = idx >> 6;         // row within tile
            int goff = (((b * NCTX + j0 + rl) * NH + hl) * WID) + wc + w4 * 4;
            float4 qv4 = *reinterpret_cast<const float4*>(q + goff);
            *reinterpret_cast<float4*>(&qs[rl * JSTR + hl * WC + w4 * 4]) = qv4;

            int koff = (((b * NCTX + i0 + rl) * NH + hl) * WID) + wc + w4 * 4;
            float4 kv4 = *reinterpret_cast<const float4*>(k + koff);
            kv4.x = -kv4.x; kv4.y = -kv4.y; kv4.z = -kv4.z; kv4.w = -kv4.w;
            *reinterpret_cast<float4*>(&ks[rl * JSTR + hl * WC + w4 * 4]) = kv4;
        }
        __syncthreads();

#pragma unroll
        for (int w4 = 0; w4 < 8; w4++) {
            unsigned long long qv[2][2], kv[4][2];
#pragma unroll
            for (int jj = 0; jj < 2; jj++) {
                ulonglong2 t = *reinterpret_cast<const ulonglong2*>(
                    &qs[(jg + 8 * jj) * JSTR + h * WC + w4 * 4]);
                qv[jj][0] = t.x; qv[jj][1] = t.y;
            }
#pragma unroll
            for (int r = 0; r < 4; r++) {
                ulonglong2 t = *reinterpret_cast<const ulonglong2*>(
                    &ks[(ig + 4 * r) * JSTR + h * WC + w4 * 4]);
                kv[r][0] = t.x; kv[r][1] = t.y;
            }
#pragma unroll
            for (int r = 0; r < 4; r++)
#pragma unroll
                for (int jj = 0; jj < 2; jj++)
#pragma unroll
                    for (int p = 0; p < 2; p++) {
                        unsigned long long d = addf32x2(qv[jj][p], kv[r][p]);
                        d &= ABSM;                       // packed |x| via 2x LOP3 (alu pipe)
                        acc[r][jj] = addf32x2(acc[r][jj], d);
                    }
        }
    }

    __syncthreads();
    // Stage results in smem (reuse qs: need 16*132=2112 <= 4160 floats)
#pragma unroll
    for (int r = 0; r < 4; r++)
#pragma unroll
        for (int jj = 0; jj < 2; jj++) {
            float lo = __uint_as_float((unsigned int)(acc[r][jj] & 0xffffffffULL));
            float hi = __uint_as_float((unsigned int)(acc[r][jj] >> 32));
            float s  = (lo + hi) * -0.125f;   // -1/sqrt(64)
            int i = ig + 4 * r;
            int j = jg + 8 * jj;
            qs[i * OSTR + j * NH + h] = s;
        }
    __syncthreads();

    // Coalesced store: each of the 16 i-rows is 128 contiguous floats (j-range x all h)
    {
        int i = tid >> 4;            // 0..15
        int c = (tid * 8) & 127;     // 0..120, float4-aligned
        const float4* src = reinterpret_cast<const float4*>(&qs[i * OSTR + c]);
        float4* dst = reinterpret_cast<float4*>(
            out + (((b * NCTX + i0 + i) * NCTX + j0) * NH) + c);
        dst[0] = src[0];
        dst[1] = src[1];
    }
}

extern "C" void kernel_launch(void* const* d_in, const int* in_sizes, int n_in,
                              void* d_out, int out_size) {
    const float* q = (const float*)d_in[0];
    const float* k = (const float*)d_in[1];
    float* out = (float*)d_out;
    int bs = in_sizes[0] / (NCTX * NH * WID);   // = 2
    dim3 grid(NCTX / TJ, NCTX / TI, bs);
    l1attn_kernel<<<grid, 256>>>(q, k, out);
}